// round 6
// baseline (speedup 1.0000x reference)
#include <cuda_runtime.h>
#include <cuda_bf16.h>

#define NN 100000
#define NE 200000
#define NG 5000
static constexpr float EPSV = 1e-5f;

// ---------------- device scratch ----------------
__device__ __align__(16) float g_T1[(size_t)NN * 128];             // [n][f*16+i] fp32
__device__ __align__(16) __nv_bfloat16 g_T2h[(size_t)NN * 256];    // [n][f*32+i] bf16 hi
__device__ __align__(16) __nv_bfloat16 g_T2l[(size_t)NN * 256];    // bf16 lo
__device__ __align__(16) float g_h1 [NN * 32];
__device__ __align__(16) float g_h1n[NN * 32];
__device__ __align__(16) __nv_bfloat16 g_h1nh[NN * 32];
__device__ __align__(16) __nv_bfloat16 g_h1nl[NN * 32];
__device__ __align__(16) float g_h2 [NN * 64];
__device__ __align__(16) float g_pooled[NG * 64];
__device__ float g_cnt[NG];
__device__ int   g_deg[NN];
__device__ int   g_indeg[NN];
__device__ int   g_off[NN];
__device__ int   g_cur[NN];
__device__ int   g_bsum[128];
__device__ int   g_boff[128];
__device__ int   g_src[NE];
__device__ __align__(16) float g_eaz[(size_t)NE * 8];
__device__ float g_stat1[64];
__device__ float g_stat2[128];
__device__ __align__(16) float g_W1p[128 * 32];            // [k=f*16+i][o] fp32 (layer1 GEMM)
__device__ __align__(16) unsigned g_B2ph[144 * 64];        // layer2 B, k-pair packed bf16 hi
__device__ __align__(16) unsigned g_B2pl[144 * 64];        // lo
__device__ __align__(16) float g_Wt1[64 * 128];
__device__ __align__(16) float g_Wt2[128 * 128];

__device__ __forceinline__ void red_v4(float* p, float4 v) {
    asm volatile("red.global.add.v4.f32 [%0], {%1,%2,%3,%4};"
                 :: "l"(p), "f"(v.x), "f"(v.y), "f"(v.z), "f"(v.w) : "memory");
}

__device__ __forceinline__ void mma_bf16(float* d, unsigned a0, unsigned a1,
                                         unsigned a2, unsigned a3,
                                         unsigned b0, unsigned b1) {
    asm volatile(
        "mma.sync.aligned.m16n8k16.row.col.f32.bf16.bf16.f32 "
        "{%0,%1,%2,%3}, {%4,%5,%6,%7}, {%8,%9}, {%0,%1,%2,%3};\n"
        : "+f"(d[0]), "+f"(d[1]), "+f"(d[2]), "+f"(d[3])
        : "r"(a0), "r"(a1), "r"(a2), "r"(a3), "r"(b0), "r"(b1));
}

__device__ __forceinline__ uint2 pack4bf(__nv_bfloat16 a, __nv_bfloat16 b,
                                         __nv_bfloat16 c, __nv_bfloat16 d) {
    uint2 r;
    r.x = (unsigned)__bfloat16_as_ushort(a) | ((unsigned)__bfloat16_as_ushort(b) << 16);
    r.y = (unsigned)__bfloat16_as_ushort(c) | ((unsigned)__bfloat16_as_ushort(d) << 16);
    return r;
}

// ---------------- init ----------------
__global__ void k_init() {
    int idx = blockIdx.x * blockDim.x + threadIdx.x;
    int stride = gridDim.x * blockDim.x;
    for (int j = idx; j < NG * 64; j += stride) g_pooled[j] = 0.f;
    for (int j = idx; j < NG;      j += stride) g_cnt[j] = 0.f;
    for (int j = idx; j < NN;      j += stride) { g_deg[j] = 0; g_indeg[j] = 0; }
    if (idx < 64)  g_stat1[idx] = 0.f;
    if (idx < 128) g_stat2[idx] = 0.f;
}

// ---------------- weight prep ----------------
// seg0: W1p (4096) | seg1: B2 pack (9216) | seg2: Wt1 (8192) | seg3: Wt2 (16384)
__global__ void k_prep(const float* __restrict__ We1, const float* __restrict__ We2,
                       const float* __restrict__ Wr2,
                       const float* __restrict__ Wf1, const float* __restrict__ Wf2) {
    int idx = blockIdx.x * blockDim.x + threadIdx.x;
    if (idx < 128 * 32) {
        int k = idx >> 5, o = idx & 31;
        int f = k >> 4, i = k & 15;
        g_W1p[idx] = We1[((o << 4) + i) * 8 + f];
    }
    int r = idx - 128 * 32;
    if (r >= 0 && r < 144 * 64) {
        int kp = r >> 6, o = r & 63;
        float w[2];
        #pragma unroll
        for (int c = 0; c < 2; c++) {
            int k = 2 * kp + c;
            if (k < 256) {
                int f = k >> 5, i = k & 31;
                w[c] = We2[((o << 5) + i) * 8 + f];
            } else {
                w[c] = Wr2[o * 32 + (k - 256)];
            }
        }
        __nv_bfloat16 h0 = __float2bfloat16(w[0]);
        __nv_bfloat16 h1 = __float2bfloat16(w[1]);
        __nv_bfloat16 l0 = __float2bfloat16(w[0] - __bfloat162float(h0));
        __nv_bfloat16 l1 = __float2bfloat16(w[1] - __bfloat162float(h1));
        g_B2ph[r] = (unsigned)__bfloat16_as_ushort(h0) | ((unsigned)__bfloat16_as_ushort(h1) << 16);
        g_B2pl[r] = (unsigned)__bfloat16_as_ushort(l0) | ((unsigned)__bfloat16_as_ushort(l1) << 16);
    }
    int p = idx - (128 * 32 + 144 * 64);
    if (p >= 0 && p < 64 * 128) {
        int i = p >> 7, o = p & 127;
        g_Wt1[p] = Wf1[o * 64 + i];
    }
    int q = idx - (128 * 32 + 144 * 64 + 64 * 128);
    if (q >= 0 && q < 128 * 128) {
        int i = q >> 7, o = q & 127;
        g_Wt2[q] = Wf2[o * 128 + i];
    }
}

// ---------------- degree counts ----------------
__global__ void k_degs(const int* __restrict__ ei) {
    int e = blockIdx.x * blockDim.x + threadIdx.x;
    if (e < NE) {
        atomicAdd(&g_deg[ei[e]], 1);
        atomicAdd(&g_indeg[ei[NE + e]], 1);
    }
}

// ---------------- scan (3 kernels) ----------------
#define SCAN_NB 98
__global__ void k_scan_a() {
    __shared__ int ss[256];
    int b = blockIdx.x, t = threadIdx.x;
    int base = b * 1024 + t * 4;
    int s = 0;
    #pragma unroll
    for (int c = 0; c < 4; c++) { int i = base + c; if (i < NN) s += g_indeg[i]; }
    ss[t] = s; __syncthreads();
    for (int off = 128; off >= 1; off >>= 1) {
        if (t < off) ss[t] += ss[t + off];
        __syncthreads();
    }
    if (t == 0) g_bsum[b] = ss[0];
}
__global__ void k_scan_b() {
    __shared__ int sb[SCAN_NB];
    int t = threadIdx.x;
    if (t < SCAN_NB) sb[t] = g_bsum[t];
    __syncthreads();
    if (t == 0) {
        int run = 0;
        for (int i = 0; i < SCAN_NB; i++) { int v = sb[i]; sb[i] = run; run += v; }
    }
    __syncthreads();
    if (t < SCAN_NB) g_boff[t] = sb[t];
}
__global__ void k_scan_c() {
    __shared__ int ss[256];
    int b = blockIdx.x, t = threadIdx.x;
    int base = b * 1024 + t * 4;
    int v[4]; int s = 0;
    #pragma unroll
    for (int c = 0; c < 4; c++) { int i = base + c; v[c] = (i < NN) ? g_indeg[i] : 0; s += v[c]; }
    ss[t] = s; __syncthreads();
    for (int off = 1; off < 256; off <<= 1) {
        int add = (t >= off) ? ss[t - off] : 0;
        __syncthreads();
        ss[t] += add;
        __syncthreads();
    }
    int run = g_boff[b] + ss[t] - s;
    #pragma unroll
    for (int c = 0; c < 4; c++) {
        int i = base + c;
        if (i < NN) { g_off[i] = run; g_cur[i] = run; run += v[c]; }
    }
}

// ---------------- fill ----------------
__global__ void k_fill(const int* __restrict__ ei, const float* __restrict__ ea) {
    int e = blockIdx.x * blockDim.x + threadIdx.x;
    if (e >= NE) return;
    int s = ei[e], d = ei[NE + e];
    float nrm = 1.0f / (float)g_deg[s];
    int pos = atomicAdd(&g_cur[d], 1);
    g_src[pos] = s;
    float4 a0 = __ldg((const float4*)(ea + (size_t)e * 8));
    float4 a1 = __ldg((const float4*)(ea + (size_t)e * 8 + 4));
    a0.x *= nrm; a0.y *= nrm; a0.z *= nrm; a0.w *= nrm;
    a1.x *= nrm; a1.y *= nrm; a1.z *= nrm; a1.w *= nrm;
    *(float4*)(g_eaz + (size_t)pos * 8)     = a0;
    *(float4*)(g_eaz + (size_t)pos * 8 + 4) = a1;
}

// ---------------- gather build T1 (fp32): 4 threads per node ----------------
__global__ __launch_bounds__(256) void k_gath1(const float* __restrict__ x) {
    int tid = blockIdx.x * 256 + threadIdx.x;
    int gn = tid >> 2, j = tid & 3;
    if (gn >= NN) return;
    float acc[32];
    #pragma unroll
    for (int q = 0; q < 32; q++) acc[q] = 0.f;
    int start = g_off[gn], cnt = g_indeg[gn];
    for (int q = 0; q < cnt; q++) {
        int pos = start + q;
        int s = __ldg(g_src + pos);
        float4 xv = __ldg((const float4*)(x + (size_t)s * 16 + j * 4));
        float4 e0 = __ldg((const float4*)(g_eaz + (size_t)pos * 8));
        float4 e1 = __ldg((const float4*)(g_eaz + (size_t)pos * 8 + 4));
        const float ef[8] = {e0.x, e0.y, e0.z, e0.w, e1.x, e1.y, e1.z, e1.w};
        #pragma unroll
        for (int f = 0; f < 8; f++) {
            acc[f * 4 + 0] += ef[f] * xv.x;
            acc[f * 4 + 1] += ef[f] * xv.y;
            acc[f * 4 + 2] += ef[f] * xv.z;
            acc[f * 4 + 3] += ef[f] * xv.w;
        }
    }
    float* dst = g_T1 + (size_t)gn * 128 + j * 4;
    #pragma unroll
    for (int f = 0; f < 8; f++)
        *(float4*)(dst + f * 16) =
            make_float4(acc[f * 4], acc[f * 4 + 1], acc[f * 4 + 2], acc[f * 4 + 3]);
}

// ---------------- gather build T2 (bf16 hi/lo): 8 threads per node ----------
__global__ __launch_bounds__(256) void k_gath2() {
    int tid = blockIdx.x * 256 + threadIdx.x;
    int gn = tid >> 3, j = tid & 7;
    if (gn >= NN) return;
    float acc[32];
    #pragma unroll
    for (int q = 0; q < 32; q++) acc[q] = 0.f;
    int start = g_off[gn], cnt = g_indeg[gn];
    for (int q = 0; q < cnt; q++) {
        int pos = start + q;
        int s = __ldg(g_src + pos);
        float4 hv = __ldg((const float4*)(g_h1n + (size_t)s * 32 + j * 4));
        float4 e0 = __ldg((const float4*)(g_eaz + (size_t)pos * 8));
        float4 e1 = __ldg((const float4*)(g_eaz + (size_t)pos * 8 + 4));
        const float ef[8] = {e0.x, e0.y, e0.z, e0.w, e1.x, e1.y, e1.z, e1.w};
        #pragma unroll
        for (int f = 0; f < 8; f++) {
            acc[f * 4 + 0] += ef[f] * hv.x;
            acc[f * 4 + 1] += ef[f] * hv.y;
            acc[f * 4 + 2] += ef[f] * hv.z;
            acc[f * 4 + 3] += ef[f] * hv.w;
        }
    }
    size_t base = (size_t)gn * 256 + j * 4;
    #pragma unroll
    for (int f = 0; f < 8; f++) {
        __nv_bfloat16 hh[4], ll[4];
        #pragma unroll
        for (int c = 0; c < 4; c++) {
            float v = acc[f * 4 + c];
            hh[c] = __float2bfloat16(v);
            ll[c] = __float2bfloat16(v - __bfloat162float(hh[c]));
        }
        *(uint2*)(g_T2h + base + f * 32) = pack4bf(hh[0], hh[1], hh[2], hh[3]);
        *(uint2*)(g_T2l + base + f * 32) = pack4bf(ll[0], ll[1], ll[2], ll[3]);
    }
}

// ---------------- GEMM layer1 (fp32 FFMA, unchanged structure) --------------
__global__ __launch_bounds__(128) void k_gemm_l1(const float* __restrict__ x,
                                                 const float* __restrict__ Wr1,
                                                 const float* __restrict__ b1) {
    __shared__ float As[32 * 132];
    __shared__ float Bs[32 * 32];
    __shared__ float s_sum[32], s_sq[32];
    int tid = threadIdx.x;
    if (tid < 32) { s_sum[tid] = 0.f; s_sq[tid] = 0.f; }
    int n0 = blockIdx.x * 128;
    int tn = tid >> 3, to = tid & 7;

    float acc[8][4];
    #pragma unroll
    for (int m = 0; m < 8; m++)
        #pragma unroll
        for (int j = 0; j < 4; j++) acc[m][j] = 0.f;

    for (int ks = 0; ks < 4; ks++) {
        __syncthreads();
        int kq = tid & 7, rr = tid >> 3;
        #pragma unroll
        for (int it = 0; it < 8; it++) {
            int row = it * 16 + rr;
            int gn = n0 + row;
            float4 v = make_float4(0, 0, 0, 0);
            if (gn < NN) v = *(const float4*)(g_T1 + (size_t)gn * 128 + ks * 32 + kq * 4);
            As[(kq * 4 + 0) * 132 + row] = v.x;
            As[(kq * 4 + 1) * 132 + row] = v.y;
            As[(kq * 4 + 2) * 132 + row] = v.z;
            As[(kq * 4 + 3) * 132 + row] = v.w;
        }
        for (int t = tid; t < 32 * 32; t += 128) Bs[t] = g_W1p[ks * 32 * 32 + t];
        __syncthreads();
        #pragma unroll
        for (int k = 0; k < 32; k++) {
            float4 b = *(const float4*)(Bs + k * 32 + to * 4);
            float4 a0 = *(const float4*)(As + k * 132 + tn * 8);
            float4 a1 = *(const float4*)(As + k * 132 + tn * 8 + 4);
            const float av[8] = {a0.x, a0.y, a0.z, a0.w, a1.x, a1.y, a1.z, a1.w};
            #pragma unroll
            for (int m = 0; m < 8; m++) {
                acc[m][0] += av[m] * b.x; acc[m][1] += av[m] * b.y;
                acc[m][2] += av[m] * b.z; acc[m][3] += av[m] * b.w;
            }
        }
    }
    {
        __syncthreads();
        int kq = tid & 3, rr = tid >> 2;
        #pragma unroll
        for (int it = 0; it < 4; it++) {
            int row = it * 32 + rr;
            int gn = n0 + row;
            float4 v = make_float4(0, 0, 0, 0);
            if (gn < NN) v = *(const float4*)(x + (size_t)gn * 16 + kq * 4);
            As[(kq * 4 + 0) * 132 + row] = v.x;
            As[(kq * 4 + 1) * 132 + row] = v.y;
            As[(kq * 4 + 2) * 132 + row] = v.z;
            As[(kq * 4 + 3) * 132 + row] = v.w;
        }
        for (int t = tid; t < 512; t += 128) {
            int o = t & 31, k = t >> 5;
            Bs[k * 32 + o] = Wr1[o * 16 + k];
        }
        __syncthreads();
        #pragma unroll
        for (int k = 0; k < 16; k++) {
            float4 b = *(const float4*)(Bs + k * 32 + to * 4);
            float4 a0 = *(const float4*)(As + k * 132 + tn * 8);
            float4 a1 = *(const float4*)(As + k * 132 + tn * 8 + 4);
            const float av[8] = {a0.x, a0.y, a0.z, a0.w, a1.x, a1.y, a1.z, a1.w};
            #pragma unroll
            for (int m = 0; m < 8; m++) {
                acc[m][0] += av[m] * b.x; acc[m][1] += av[m] * b.y;
                acc[m][2] += av[m] * b.z; acc[m][3] += av[m] * b.w;
            }
        }
    }
    float bv[4];
    #pragma unroll
    for (int j = 0; j < 4; j++) bv[j] = __ldg(b1 + to * 4 + j);
    float ls[4] = {0, 0, 0, 0}, lq[4] = {0, 0, 0, 0};
    #pragma unroll
    for (int m = 0; m < 8; m++) {
        int gn = n0 + tn * 8 + m;
        if (gn < NN) {
            float4 h;
            h.x = acc[m][0] + bv[0]; h.y = acc[m][1] + bv[1];
            h.z = acc[m][2] + bv[2]; h.w = acc[m][3] + bv[3];
            *(float4*)(g_h1 + (size_t)gn * 32 + to * 4) = h;
            ls[0] += h.x; ls[1] += h.y; ls[2] += h.z; ls[3] += h.w;
            lq[0] += h.x * h.x; lq[1] += h.y * h.y; lq[2] += h.z * h.z; lq[3] += h.w * h.w;
        }
    }
    #pragma unroll
    for (int j = 0; j < 4; j++) {
        atomicAdd(&s_sum[to * 4 + j], ls[j]);
        atomicAdd(&s_sq [to * 4 + j], lq[j]);
    }
    __syncthreads();
    if (tid < 32) {
        atomicAdd(&g_stat1[tid],      s_sum[tid]);
        atomicAdd(&g_stat1[32 + tid], s_sq[tid]);
    }
}

// ---------------- GEMM layer2: tensor-core bf16 split ----------------
// C[128 nodes][64 outs] per block; 8 warps, warp w owns rows w*16..w*16+15.
// K=288 (256 T2 + 32 h1n), staged 32-K at a time; B resident in smem.
// Bsh/Bsl: [144][72] uint32 (padded); Ash/Asl: [128][40] bf16 (stride 40 = 80B).
#define L2_SMEM_BYTES (144 * 72 * 4 * 2 + 128 * 40 * 2 * 2)
__global__ __launch_bounds__(256) void k_gemm_l2t(const float* __restrict__ b2) {
    extern __shared__ unsigned char smraw[];
    unsigned* Bsh = (unsigned*)smraw;                         // 144*72
    unsigned* Bsl = Bsh + 144 * 72;
    __nv_bfloat16* Ash = (__nv_bfloat16*)(Bsl + 144 * 72);    // 128*40
    __nv_bfloat16* Asl = Ash + 128 * 40;
    __shared__ float s_sum[64], s_sq[64];
    int tid = threadIdx.x;
    int n0 = blockIdx.x * 128;
    int warp = tid >> 5, lane = tid & 31;
    int qr = lane >> 2, qc = lane & 3;

    for (int t = tid; t < 144 * 64; t += 256) {
        int kp = t >> 6, o = t & 63;
        Bsh[kp * 72 + o] = g_B2ph[t];
        Bsl[kp * 72 + o] = g_B2pl[t];
    }
    if (tid < 64) { s_sum[tid] = 0.f; s_sq[tid] = 0.f; }

    float d[8][4];
    #pragma unroll
    for (int t8 = 0; t8 < 8; t8++)
        #pragma unroll
        for (int c = 0; c < 4; c++) d[t8][c] = 0.f;

    int lrow = tid >> 1, lpart = tid & 1;   // stage-load mapping: 2 threads/row
    for (int ss = 0; ss < 9; ss++) {
        __syncthreads();
        {
            int gn = n0 + lrow;
            uint4 vh0 = make_uint4(0,0,0,0), vh1 = vh0, vl0 = vh0, vl1 = vh0;
            if (gn < NN) {
                const __nv_bfloat16 *sh, *sl;
                if (ss < 8) {
                    sh = g_T2h + (size_t)gn * 256 + ss * 32 + lpart * 16;
                    sl = g_T2l + (size_t)gn * 256 + ss * 32 + lpart * 16;
                } else {
                    sh = g_h1nh + (size_t)gn * 32 + lpart * 16;
                    sl = g_h1nl + (size_t)gn * 32 + lpart * 16;
                }
                vh0 = __ldg((const uint4*)sh);     vh1 = __ldg((const uint4*)sh + 1);
                vl0 = __ldg((const uint4*)sl);     vl1 = __ldg((const uint4*)sl + 1);
            }
            __nv_bfloat16* da = Ash + lrow * 40 + lpart * 16;
            *(uint4*)da = vh0; *((uint4*)da + 1) = vh1;
            __nv_bfloat16* dl = Asl + lrow * 40 + lpart * 16;
            *(uint4*)dl = vl0; *((uint4*)dl + 1) = vl1;
        }
        __syncthreads();
        #pragma unroll
        for (int h = 0; h < 2; h++) {
            int abase = (warp * 16 + qr) * 40 + h * 16 + qc * 2;
            unsigned ah0 = *(unsigned*)(Ash + abase);
            unsigned ah1 = *(unsigned*)(Ash + abase + 8 * 40);
            unsigned ah2 = *(unsigned*)(Ash + abase + 8);
            unsigned ah3 = *(unsigned*)(Ash + abase + 8 * 40 + 8);
            unsigned al0 = *(unsigned*)(Asl + abase);
            unsigned al1 = *(unsigned*)(Asl + abase + 8 * 40);
            unsigned al2 = *(unsigned*)(Asl + abase + 8);
            unsigned al3 = *(unsigned*)(Asl + abase + 8 * 40 + 8);
            int kp0 = ss * 16 + h * 8 + qc;
            const unsigned* bh = Bsh + kp0 * 72;
            const unsigned* bl = Bsl + kp0 * 72;
            #pragma unroll
            for (int t8 = 0; t8 < 8; t8++) {
                int nn = t8 * 8 + qr;
                unsigned bh0 = bh[nn], bh1 = bh[4 * 72 + nn];
                unsigned bl0 = bl[nn], bl1 = bl[4 * 72 + nn];
                mma_bf16(d[t8], ah0, ah1, ah2, ah3, bh0, bh1);
                mma_bf16(d[t8], ah0, ah1, ah2, ah3, bl0, bl1);
                mma_bf16(d[t8], al0, al1, al2, al3, bh0, bh1);
            }
        }
    }

    // epilogue: bias, store h2, BN stats
    int r0 = n0 + warp * 16 + qr;
    int r1 = r0 + 8;
    bool v0 = r0 < NN, v1 = r1 < NN;
    #pragma unroll
    for (int t8 = 0; t8 < 8; t8++) {
        int cA = t8 * 8 + qc * 2;
        float bvA = __ldg(b2 + cA), bvB = __ldg(b2 + cA + 1);
        float h0 = d[t8][0] + bvA, h1 = d[t8][1] + bvB;
        float h2v = d[t8][2] + bvA, h3 = d[t8][3] + bvB;
        if (v0) { float2 st = make_float2(h0, h1); *(float2*)(g_h2 + (size_t)r0 * 64 + cA) = st; }
        if (v1) { float2 st = make_float2(h2v, h3); *(float2*)(g_h2 + (size_t)r1 * 64 + cA) = st; }
        float sA = (v0 ? h0 : 0.f) + (v1 ? h2v : 0.f);
        float sB = (v0 ? h1 : 0.f) + (v1 ? h3 : 0.f);
        float qA = (v0 ? h0 * h0 : 0.f) + (v1 ? h2v * h2v : 0.f);
        float qB = (v0 ? h1 * h1 : 0.f) + (v1 ? h3 * h3 : 0.f);
        atomicAdd(&s_sum[cA], sA); atomicAdd(&s_sum[cA + 1], sB);
        atomicAdd(&s_sq[cA], qA);  atomicAdd(&s_sq[cA + 1], qB);
    }
    __syncthreads();
    if (tid < 64) {
        atomicAdd(&g_stat2[tid],      s_sum[tid]);
        atomicAdd(&g_stat2[64 + tid], s_sq[tid]);
    }
}

// ---------------- BN1 apply + relu -> h1n (fp32 + bf16 split) ----------------
__global__ void k_bn1(const float* __restrict__ g1, const float* __restrict__ be1) {
    int idx = blockIdx.x * blockDim.x + threadIdx.x;
    if (idx >= NN * 8) return;
    int n = idx >> 3, q = idx & 7;
    const float invN = 1.0f / (float)NN;
    float4 h = *(const float4*)(g_h1 + (size_t)n * 32 + q * 4);
    float4 v;
    float* hv = (float*)&h; float* vv = (float*)&v;
    __nv_bfloat16 hh[4], ll[4];
    #pragma unroll
    for (int j = 0; j < 4; j++) {
        int c = q * 4 + j;
        float mu = g_stat1[c] * invN;
        float var = g_stat1[32 + c] * invN - mu * mu;
        float rs = rsqrtf(var + EPSV);
        float val = fmaxf((hv[j] - mu) * rs * __ldg(g1 + c) + __ldg(be1 + c), 0.f);
        vv[j] = val;
        hh[j] = __float2bfloat16(val);
        ll[j] = __float2bfloat16(val - __bfloat162float(hh[j]));
    }
    *(float4*)(g_h1n + (size_t)n * 32 + q * 4) = v;
    *(uint2*)(g_h1nh + (size_t)n * 32 + q * 4) = pack4bf(hh[0], hh[1], hh[2], hh[3]);
    *(uint2*)(g_h1nl + (size_t)n * 32 + q * 4) = pack4bf(ll[0], ll[1], ll[2], ll[3]);
}

// ---------------- BN2 apply + relu + pooling ----------------
__global__ void k_bn2pool(const float* __restrict__ g2, const float* __restrict__ be2,
                          const int* __restrict__ batch) {
    int idx = blockIdx.x * blockDim.x + threadIdx.x;
    if (idx >= NN * 16) return;
    int n = idx >> 4, q = idx & 15;
    const float invN = 1.0f / (float)NN;
    float4 h = *(const float4*)(g_h2 + (size_t)n * 64 + q * 4);
    float4 v;
    float* hv = (float*)&h; float* vv = (float*)&v;
    #pragma unroll
    for (int j = 0; j < 4; j++) {
        int c = q * 4 + j;
        float mu = g_stat2[c] * invN;
        float var = g_stat2[64 + c] * invN - mu * mu;
        float rs = rsqrtf(var + EPSV);
        vv[j] = fmaxf((hv[j] - mu) * rs * __ldg(g2 + c) + __ldg(be2 + c), 0.f);
    }
    int b = batch[n];
    red_v4(g_pooled + (size_t)b * 64 + q * 4, v);
    if (q == 0) atomicAdd(&g_cnt[b], 1.0f);
}

// ---------------- final MLP ----------------
__global__ __launch_bounds__(128) void k_fc(const float* __restrict__ bf1,
                                            const float* __restrict__ bf2,
                                            float* __restrict__ out) {
    __shared__ float pm[8][64];
    __shared__ float hid[8][128];
    int tid = threadIdx.x;
    int g0 = blockIdx.x * 8;
    for (int t = tid; t < 512; t += 128) {
        int gg = t >> 6, i = t & 63;
        int g = g0 + gg;
        pm[gg][i] = g_pooled[g * 64 + i] / fmaxf(g_cnt[g], 1.0f);
    }
    __syncthreads();

    float acc[8];
    float b = bf1[tid];
    #pragma unroll
    for (int gg = 0; gg < 8; gg++) acc[gg] = b;
    for (int i = 0; i < 64; i++) {
        float w = g_Wt1[i * 128 + tid];
        #pragma unroll
        for (int gg = 0; gg < 8; gg++) acc[gg] += w * pm[gg][i];
    }
    #pragma unroll
    for (int gg = 0; gg < 8; gg++) hid[gg][tid] = fmaxf(acc[gg], 0.f);
    __syncthreads();

    float b2v = bf2[tid];
    #pragma unroll
    for (int gg = 0; gg < 8; gg++) acc[gg] = b2v;
    for (int i = 0; i < 128; i++) {
        float w = g_Wt2[i * 128 + tid];
        #pragma unroll
        for (int gg = 0; gg < 8; gg++) acc[gg] += w * hid[gg][i];
    }
    #pragma unroll
    for (int gg = 0; gg < 8; gg++) {
        int g = g0 + gg;
        if (tid < 64) out[g * 64 + tid] = acc[gg];
        else          out[NG * 64 + g * 64 + (tid - 64)] = acc[gg];
    }
}

// ---------------- launch ----------------
extern "C" void kernel_launch(void* const* d_in, const int* in_sizes, int n_in,
                              void* d_out, int out_size) {
    const float* x    = (const float*)d_in[0];
    const int*   ei   = (const int*)  d_in[1];
    const float* ea   = (const float*)d_in[2];
    const int*   batch= (const int*)  d_in[3];
    const float* We1  = (const float*)d_in[4];
    const float* b1   = (const float*)d_in[5];
    const float* Wr1  = (const float*)d_in[6];
    const float* g1   = (const float*)d_in[7];
    const float* be1  = (const float*)d_in[8];
    const float* We2  = (const float*)d_in[9];
    const float* b2   = (const float*)d_in[10];
    const float* Wr2  = (const float*)d_in[11];
    const float* g2   = (const float*)d_in[12];
    const float* be2  = (const float*)d_in[13];
    const float* Wf1  = (const float*)d_in[14];
    const float* bf1  = (const float*)d_in[15];
    const float* Wf2  = (const float*)d_in[16];
    const float* bf2  = (const float*)d_in[17];
    float* out = (float*)d_out;

    static int attr_set = 0;
    if (!attr_set) {
        cudaFuncSetAttribute(k_gemm_l2t, cudaFuncAttributeMaxDynamicSharedMemorySize,
                             L2_SMEM_BYTES);
        attr_set = 1;
    }

    k_init<<<256, 256>>>();
    k_prep<<<(128 * 32 + 144 * 64 + 64 * 128 + 128 * 128 + 255) / 256, 256>>>(We1, We2, Wr2, Wf1, Wf2);
    k_degs<<<(NE + 255) / 256, 256>>>(ei);
    k_scan_a<<<SCAN_NB, 256>>>();
    k_scan_b<<<1, 128>>>();
    k_scan_c<<<SCAN_NB, 256>>>();
    k_fill<<<(NE + 255) / 256, 256>>>(ei, ea);
    k_gath1<<<(NN * 4 + 255) / 256, 256>>>(x);
    k_gemm_l1<<<(NN + 127) / 128, 128>>>(x, Wr1, b1);
    k_bn1<<<(NN * 8 + 255) / 256, 256>>>(g1, be1);
    k_gath2<<<(NN * 8 + 255) / 256, 256>>>();
    k_gemm_l2t<<<(NN + 127) / 128, 256, L2_SMEM_BYTES>>>(b2);
    k_bn2pool<<<(NN * 16 + 255) / 256, 256>>>(g2, be2, batch);
    k_fc<<<NG / 8, 128>>>(bf1, bf2, out);
}